// round 15
// baseline (speedup 1.0000x reference)
#include <cuda_runtime.h>
#include <cuda_bf16.h>
#include <math.h>
#include <stdint.h>

#define N_NODES 50000
#define N_EDGES 800000
#define NB_SCAN 196   // ceil(50000 / 256)
// dims: IN=256, EMB1=128, EMB2=64, L1=64

// ---------------- device scratch ----------------
__device__ float g_xr1 [(size_t)N_NODES * 128];
__device__ float g_h   [(size_t)N_NODES * 128];   // root1+b1, then lrelu(h) in-place
__device__ float g_zr  [(size_t)N_NODES * 64];
__device__ float g_zbuf[(size_t)N_NODES * 64];
__device__ float g_z   [(size_t)N_NODES * 64];
__device__ float g_gr  [(size_t)N_NODES * 64];
__device__ float g_gbuf[(size_t)N_NODES * 64];
__device__ float g_srel[N_NODES];
__device__ float g_gate[N_NODES];                 // root part of gate (from gather_g)
__device__ float g_norm[N_NODES];
__device__ float g_pool[64];
__device__ float g_scal[2];
__device__ int g_poolcnt;   // zero-init; reset by last pool block
// CSR  (g_cnt zero-init; lscan2 re-zeroes each call)
__device__ int g_cnt[N_NODES];
__device__ int g_rs[N_NODES + 1];
__device__ int g_fill[N_NODES];
__device__ int g_dst[N_EDGES];
__device__ int g_bsum[NB_SCAN];

__device__ __forceinline__ float lrelu(float v) { return v > 0.f ? v : 0.2f * v; }

// pack two floats -> bf16x2 hi (returned) and bf16x2 lo (out-param)
__device__ __forceinline__ uint32_t packhl(float a, float b, uint32_t& lo) {
    __nv_bfloat162 h2 = __floats2bfloat162_rn(a, b);
    uint32_t hu = *reinterpret_cast<uint32_t*>(&h2);
    float ra = __uint_as_float(hu << 16);
    float rb = __uint_as_float(hu & 0xFFFF0000u);
    __nv_bfloat162 l2 = __floats2bfloat162_rn(a - ra, b - rb);
    lo = *reinterpret_cast<uint32_t*>(&l2);
    return hu;
}
__device__ __forceinline__ void cvt8(const float4& v0, const float4& v1, uint4& hi, uint4& lo) {
    hi.x = packhl(v0.x, v0.y, lo.x);
    hi.y = packhl(v0.z, v0.w, lo.y);
    hi.z = packhl(v1.x, v1.y, lo.z);
    hi.w = packhl(v1.z, v1.w, lo.w);
}

#define MMA_BF16(c0, c1, c2, c3, a0, a1, a2, a3, b0, b1)                          \
    asm volatile("mma.sync.aligned.m16n8k16.row.col.f32.bf16.bf16.f32 "           \
                 "{%0,%1,%2,%3}, {%4,%5,%6,%7}, {%8,%9}, {%0,%1,%2,%3};"          \
                 : "+f"(c0), "+f"(c1), "+f"(c2), "+f"(c3)                         \
                 : "r"(a0), "r"(a1), "r"(a2), "r"(a3), "r"(b0), "r"(b1))

// ---------------- CSR build ----------------
__global__ void hist_kernel(const int* __restrict__ row) {
    int e = blockIdx.x * blockDim.x + threadIdx.x;
    if (e < N_EDGES) atomicAdd(&g_cnt[__ldg(&row[e])], 1);
}

__global__ void bsum_kernel() {
    __shared__ int sm[256];
    int t = threadIdx.x;
    int idx = blockIdx.x * 256 + t;
    sm[t] = (idx < N_NODES) ? g_cnt[idx] : 0;
    __syncthreads();
    for (int s = 128; s > 0; s >>= 1) {
        if (t < s) sm[t] += sm[t + s];
        __syncthreads();
    }
    if (t == 0) g_bsum[blockIdx.x] = sm[0];
    if (blockIdx.x == 0) {
        if (t < 64) g_pool[t] = 0.f;
        if (t == 64) g_scal[1] = 0.f;
    }
}

__global__ void lscan2_kernel() {
    __shared__ int pre[256];
    __shared__ int sm[256];
    int t = threadIdx.x, bid = blockIdx.x;
    pre[t] = (t < bid) ? g_bsum[t] : 0;
    __syncthreads();
    for (int s = 128; s > 0; s >>= 1) {
        if (t < s) pre[t] += pre[t + s];
        __syncthreads();
    }
    int boff = pre[0];
    int idx = bid * 256 + t;
    int v = (idx < N_NODES) ? g_cnt[idx] : 0;
    sm[t] = v;
    __syncthreads();
    for (int off = 1; off < 256; off <<= 1) {
        int u = (t >= off) ? sm[t - off] : 0;
        __syncthreads();
        sm[t] += u;
        __syncthreads();
    }
    if (idx < N_NODES) {
        int r = boff + sm[t] - v;
        g_rs[idx] = r;
        g_fill[idx] = r;
        g_cnt[idx] = 0;
    }
    if (bid == NB_SCAN - 1 && t == 255) g_rs[N_NODES] = boff + sm[255];
}

__global__ void fill_kernel(const int* __restrict__ row, const int* __restrict__ col) {
    int e = blockIdx.x * blockDim.x + threadIdx.x;
    if (e >= N_EDGES) return;
    int pos = atomicAdd(&g_fill[__ldg(&row[e])], 1);
    g_dst[pos] = __ldg(&col[e]);
}

// ------- double-buffered mma.sync bf16 hi/lo GEMM; LDG -> MMA -> STS pipeline -------
// MODE 1: A=x (K=256), BN=128, grid.x=2: bx0 w_rel1 -> g_xr1 ; bx1 w_root1 -> g_h = v + b1
// MODE 2: A=g_h (K=128), BN=64, grid.x=2: bx0 wrm -> g_zr ; bx1 wom -> g_zbuf = v+b_mu
// MODE 3: A=g_z (K=64),  BN=64, grid.x=2: bx0 wrg1 -> g_gr ; bx1 wog1 -> g_gbuf = v+b_g1
// MODE 4: A=g_h (K=128), BN=64, grid.x=1: W0=w_std -> out_extra = exp(tanh(v+b_std))
template <int MODE>
__global__ __launch_bounds__(256)
void mma_gemm_kernel(const float* __restrict__ Ax,
                     const float* __restrict__ W0, const float* __restrict__ W1,
                     const float* __restrict__ bias0,
                     float* __restrict__ out_extra) {
    constexpr int K   = (MODE == 1) ? 256 : (MODE == 3) ? 64 : 128;
    constexpr int BN  = (MODE == 1) ? 128 : 64;
    constexpr int JT  = BN / 16;
    constexpr int NST = K / 32;
    constexpr int AP  = 40;
    constexpr int ASZ = 128 * AP;
    constexpr int BSZ = BN * AP;
    constexpr int BIT = BN / 64;

    extern __shared__ __align__(16) __nv_bfloat16 smArr[];
    __nv_bfloat16* Ah = smArr;
    __nv_bfloat16* Al = Ah + 2 * ASZ;
    __nv_bfloat16* Bh = Al + 2 * ASZ;
    __nv_bfloat16* Bl = Bh + 2 * BSZ;

    const float* A = (MODE == 1) ? Ax : (MODE == 3) ? (const float*)g_z : (const float*)g_h;
    const float* W = (blockIdx.x == 0) ? W0 : W1;

    const int tid = threadIdx.x;
    const int wid = tid >> 5, lane = tid & 31;
    const int wm = wid & 3, wn = wid >> 2;
    const int g = lane >> 2, tq = lane & 3;
    const int row0 = blockIdx.y * 128;
    const int col0 = blockIdx.x * BN;
    const int rm = wm * 32, cn = wn * (BN / 2);
    const int ra = tid >> 2;
    const int ch = (tid & 3) * 8;

    float acc[2][JT][4];
#pragma unroll
    for (int i = 0; i < 2; i++)
#pragma unroll
        for (int j = 0; j < JT; j++)
#pragma unroll
            for (int p = 0; p < 4; p++) acc[i][j][p] = 0.f;

    float4 av[2][2], bv[BIT][2];

    auto ldg_stage = [&](int s) {
        int k0 = s * 32;
#pragma unroll
        for (int it = 0; it < 2; it++) {
            int grow = row0 + ra + it * 64;
            if (grow >= N_NODES) grow = N_NODES - 1;
            const float4* src = (const float4*)&A[(size_t)grow * K + k0 + ch];
            av[it][0] = src[0]; av[it][1] = src[1];
        }
#pragma unroll
        for (int it = 0; it < BIT; it++) {
            const float4* src = (const float4*)&W[(size_t)(ra + it * 64) * K + k0 + ch];
            bv[it][0] = src[0]; bv[it][1] = src[1];
        }
    };
    auto sts_stage = [&](int s) {
        int buf = s & 1;
#pragma unroll
        for (int it = 0; it < 2; it++) {
            uint4 hi, lo;
            cvt8(av[it][0], av[it][1], hi, lo);
            int r = ra + it * 64;
            *(uint4*)&Ah[buf * ASZ + r * AP + ch] = hi;
            *(uint4*)&Al[buf * ASZ + r * AP + ch] = lo;
        }
#pragma unroll
        for (int it = 0; it < BIT; it++) {
            uint4 hi, lo;
            cvt8(bv[it][0], bv[it][1], hi, lo);
            int r = ra + it * 64;
            *(uint4*)&Bh[buf * BSZ + r * AP + ch] = hi;
            *(uint4*)&Bl[buf * BSZ + r * AP + ch] = lo;
        }
    };

    ldg_stage(0);
    sts_stage(0);
    __syncthreads();

    for (int s = 0; s < NST; s++) {
        if (s + 1 < NST) ldg_stage(s + 1);
        const int buf = s & 1;
        const __nv_bfloat16* cAh = Ah + buf * ASZ;
        const __nv_bfloat16* cAl = Al + buf * ASZ;
        const __nv_bfloat16* cBh = Bh + buf * BSZ;
        const __nv_bfloat16* cBl = Bl + buf * BSZ;
#pragma unroll
        for (int ks = 0; ks < 32; ks += 16) {
            uint32_t ah[2][4], al[2][4], bh[JT][2], bl[JT][2];
#pragma unroll
            for (int i = 0; i < 2; i++) {
                int r = rm + i * 16 + g;
                ah[i][0] = *(const uint32_t*)&cAh[r * AP + ks + tq * 2];
                ah[i][1] = *(const uint32_t*)&cAh[(r + 8) * AP + ks + tq * 2];
                ah[i][2] = *(const uint32_t*)&cAh[r * AP + ks + tq * 2 + 8];
                ah[i][3] = *(const uint32_t*)&cAh[(r + 8) * AP + ks + tq * 2 + 8];
                al[i][0] = *(const uint32_t*)&cAl[r * AP + ks + tq * 2];
                al[i][1] = *(const uint32_t*)&cAl[(r + 8) * AP + ks + tq * 2];
                al[i][2] = *(const uint32_t*)&cAl[r * AP + ks + tq * 2 + 8];
                al[i][3] = *(const uint32_t*)&cAl[(r + 8) * AP + ks + tq * 2 + 8];
            }
#pragma unroll
            for (int j = 0; j < JT; j++) {
                int n = cn + j * 8 + g;
                bh[j][0] = *(const uint32_t*)&cBh[n * AP + ks + tq * 2];
                bh[j][1] = *(const uint32_t*)&cBh[n * AP + ks + tq * 2 + 8];
                bl[j][0] = *(const uint32_t*)&cBl[n * AP + ks + tq * 2];
                bl[j][1] = *(const uint32_t*)&cBl[n * AP + ks + tq * 2 + 8];
            }
#pragma unroll
            for (int i = 0; i < 2; i++)
#pragma unroll
                for (int j = 0; j < JT; j++) {
                    MMA_BF16(acc[i][j][0], acc[i][j][1], acc[i][j][2], acc[i][j][3],
                             ah[i][0], ah[i][1], ah[i][2], ah[i][3], bh[j][0], bh[j][1]);
                    MMA_BF16(acc[i][j][0], acc[i][j][1], acc[i][j][2], acc[i][j][3],
                             al[i][0], al[i][1], al[i][2], al[i][3], bh[j][0], bh[j][1]);
                    MMA_BF16(acc[i][j][0], acc[i][j][1], acc[i][j][2], acc[i][j][3],
                             ah[i][0], ah[i][1], ah[i][2], ah[i][3], bl[j][0], bl[j][1]);
                }
        }
        if (s + 1 < NST) {
            sts_stage(s + 1);
            __syncthreads();
        }
    }

#pragma unroll
    for (int i = 0; i < 2; i++) {
#pragma unroll
        for (int half = 0; half < 2; half++) {
            int m = row0 + rm + i * 16 + g + half * 8;
            if (m >= N_NODES) continue;
#pragma unroll
            for (int j = 0; j < JT; j++) {
                int gcol = col0 + cn + j * 8 + tq * 2;
                float2 v = make_float2(acc[i][j][half * 2], acc[i][j][half * 2 + 1]);
                if (MODE == 1) {
                    if (gcol < 128) {
                        *(float2*)&g_xr1[(size_t)m * 128 + gcol] = v;
                    } else {
                        float2 b = *(const float2*)&bias0[gcol - 128];
                        v.x += b.x; v.y += b.y;
                        *(float2*)&g_h[(size_t)m * 128 + gcol - 128] = v;
                    }
                } else if (MODE == 2) {
                    if (gcol < 64) {
                        *(float2*)&g_zr[(size_t)m * 64 + gcol] = v;
                    } else {
                        float2 b = *(const float2*)&bias0[gcol - 64];
                        v.x += b.x; v.y += b.y;
                        *(float2*)&g_zbuf[(size_t)m * 64 + gcol - 64] = v;
                    }
                } else if (MODE == 3) {
                    if (gcol < 64) {
                        *(float2*)&g_gr[(size_t)m * 64 + gcol] = v;
                    } else {
                        float2 b = *(const float2*)&bias0[gcol - 64];
                        v.x += b.x; v.y += b.y;
                        *(float2*)&g_gbuf[(size_t)m * 64 + gcol - 64] = v;
                    }
                } else {  // MODE 4: std head
                    float2 b = *(const float2*)&bias0[gcol];
                    size_t o = (size_t)m * 64 + gcol;
                    out_extra[o + 0] = expf(tanhf(v.x + b.x));
                    out_extra[o + 1] = expf(tanhf(v.y + b.y));
                }
            }
        }
    }
}

// ---------------- CSR gathers (warp per node, fp32 messages, 4x unrolled) ----------------
__global__ void gather_h_kernel() {
    int gw = (blockIdx.x * blockDim.x + threadIdx.x) >> 5;
    int lane = threadIdx.x & 31;
    if (gw >= N_NODES) return;
    int s = g_rs[gw], e = g_rs[gw + 1];
    float4 acc = make_float4(0.f, 0.f, 0.f, 0.f);
    int i = s;
    for (; i + 4 <= e; i += 4) {
        int c0 = __ldg(&g_dst[i]),     c1 = __ldg(&g_dst[i + 1]);
        int c2 = __ldg(&g_dst[i + 2]), c3 = __ldg(&g_dst[i + 3]);
        float4 v0 = *(const float4*)&g_xr1[(size_t)c0 * 128 + lane * 4];
        float4 v1 = *(const float4*)&g_xr1[(size_t)c1 * 128 + lane * 4];
        float4 v2 = *(const float4*)&g_xr1[(size_t)c2 * 128 + lane * 4];
        float4 v3 = *(const float4*)&g_xr1[(size_t)c3 * 128 + lane * 4];
        acc.x += v0.x + v1.x + v2.x + v3.x;
        acc.y += v0.y + v1.y + v2.y + v3.y;
        acc.z += v0.z + v1.z + v2.z + v3.z;
        acc.w += v0.w + v1.w + v2.w + v3.w;
    }
    for (; i < e; i++) {
        int c = __ldg(&g_dst[i]);
        float4 v = *(const float4*)&g_xr1[(size_t)c * 128 + lane * 4];
        acc.x += v.x; acc.y += v.y; acc.z += v.z; acc.w += v.w;
    }
    size_t o = (size_t)gw * 128 + lane * 4;
    float4 h = *(const float4*)&g_h[o];
    h.x = lrelu(h.x + acc.x); h.y = lrelu(h.y + acc.y);
    h.z = lrelu(h.z + acc.z); h.w = lrelu(h.w + acc.w);
    *(float4*)&g_h[o] = h;
}

__global__ void gather_z_kernel() {
    int gw = (blockIdx.x * blockDim.x + threadIdx.x) >> 5;
    int lane = threadIdx.x & 31;
    if (gw >= N_NODES) return;
    int s = g_rs[gw], e = g_rs[gw + 1];
    float a0 = 0.f, a1 = 0.f;
    int i = s;
    for (; i + 4 <= e; i += 4) {
        int c0 = __ldg(&g_dst[i]),     c1 = __ldg(&g_dst[i + 1]);
        int c2 = __ldg(&g_dst[i + 2]), c3 = __ldg(&g_dst[i + 3]);
        float2 v0 = *(const float2*)&g_zr[(size_t)c0 * 64 + lane * 2];
        float2 v1 = *(const float2*)&g_zr[(size_t)c1 * 64 + lane * 2];
        float2 v2 = *(const float2*)&g_zr[(size_t)c2 * 64 + lane * 2];
        float2 v3 = *(const float2*)&g_zr[(size_t)c3 * 64 + lane * 2];
        a0 += v0.x + v1.x + v2.x + v3.x;
        a1 += v0.y + v1.y + v2.y + v3.y;
    }
    for (; i < e; i++) {
        int c = __ldg(&g_dst[i]);
        float2 v = *(const float2*)&g_zr[(size_t)c * 64 + lane * 2];
        a0 += v.x; a1 += v.y;
    }
    size_t o = (size_t)gw * 64 + lane * 2;
    float2 zb = *(const float2*)&g_zbuf[o];
    float z0 = tanhf(zb.x + a0), z1 = tanhf(zb.y + a1);
    *(float2*)&g_z[o] = make_float2(z0, z1);
    float ss = z0 * z0 + z1 * z1;
#pragma unroll
    for (int off = 16; off; off >>= 1) ss += __shfl_xor_sync(0xffffffffu, ss, off);
    if (lane == 0) g_norm[gw] = fmaxf(sqrtf(ss), 1e-8f);
}

// z -> out_z, out_zmu (runs on side stream)
__global__ void copyz_kernel(float* __restrict__ out_z, float* __restrict__ out_zmu) {
    int i = blockIdx.x * blockDim.x + threadIdx.x;
    if (i >= N_NODES * 64) return;
    float v = g_z[i];
    out_z[i] = v;
    out_zmu[i] = v;
}

__global__ void gather_g_kernel(const float* __restrict__ wrel2, const float* __restrict__ wroot2,
                                const float* __restrict__ bg2) {
    int gw = (blockIdx.x * blockDim.x + threadIdx.x) >> 5;
    int lane = threadIdx.x & 31;
    if (gw >= N_NODES) return;
    int s = g_rs[gw], e = g_rs[gw + 1];
    float a0 = 0.f, a1 = 0.f;
    int i = s;
    for (; i + 4 <= e; i += 4) {
        int c0 = __ldg(&g_dst[i]),     c1 = __ldg(&g_dst[i + 1]);
        int c2 = __ldg(&g_dst[i + 2]), c3 = __ldg(&g_dst[i + 3]);
        float2 v0 = *(const float2*)&g_gr[(size_t)c0 * 64 + lane * 2];
        float2 v1 = *(const float2*)&g_gr[(size_t)c1 * 64 + lane * 2];
        float2 v2 = *(const float2*)&g_gr[(size_t)c2 * 64 + lane * 2];
        float2 v3 = *(const float2*)&g_gr[(size_t)c3 * 64 + lane * 2];
        a0 += v0.x + v1.x + v2.x + v3.x;
        a1 += v0.y + v1.y + v2.y + v3.y;
    }
    for (; i < e; i++) {
        int c = __ldg(&g_dst[i]);
        float2 v = *(const float2*)&g_gr[(size_t)c * 64 + lane * 2];
        a0 += v.x; a1 += v.y;
    }
    size_t o = (size_t)gw * 64 + lane * 2;
    float2 gb = *(const float2*)&g_gbuf[o];
    float g0 = lrelu(gb.x + a0), g1 = lrelu(gb.y + a1);
    float s0 = g0 * __ldg(&wrel2[lane * 2]) + g1 * __ldg(&wrel2[lane * 2 + 1]);
    float s1 = g0 * __ldg(&wroot2[lane * 2]) + g1 * __ldg(&wroot2[lane * 2 + 1]);
#pragma unroll
    for (int off = 16; off; off >>= 1) {
        s0 += __shfl_xor_sync(0xffffffffu, s0, off);
        s1 += __shfl_xor_sync(0xffffffffu, s1, off);
    }
    if (lane == 0) {
        g_srel[gw] = s0;
        g_gate[gw] = s1 + __ldg(&bg2[0]);   // root part; edge part added in pool_final
    }
}

// ---------------- per-edge cosine similarity ----------------
__global__ void edge_cos_kernel(const int* __restrict__ row, const int* __restrict__ col,
                                float* __restrict__ wmu) {
    int e = blockIdx.x * blockDim.x + threadIdx.x;
    if (e >= N_EDGES) return;
    int r = __ldg(&row[e]);
    int c = __ldg(&col[e]);
    const float4* a = (const float4*)&g_z[(size_t)r * 64];
    const float4* b = (const float4*)&g_z[(size_t)c * 64];
    float acc = 0.f;
#pragma unroll
    for (int i = 0; i < 16; i++) {
        float4 u = __ldg(a + i), v = __ldg(b + i);
        acc += u.x * v.x + u.y * v.y + u.z * v.z + u.w * v.w;
    }
    wmu[e] = acc / (g_norm[r] * g_norm[c]);
}

// -------- fused: gate edge-aggregation + exp + weighted pool + classifier --------
// 256 threads per block, 256 nodes per block. Gate values live only in smem.
__global__ __launch_bounds__(256)
void pool_final_kernel(const float* __restrict__ w_cls1, const float* __restrict__ b_cls1,
                       const float* __restrict__ w_cls2, const float* __restrict__ b_cls2,
                       const float* __restrict__ log_std, float* __restrict__ out) {
    __shared__ float eg[256];           // exp(gate) per node in block
    __shared__ float part[4][64];
    __shared__ float pooled[64], y1s[64], y2s[2];
    __shared__ int slast;
    int t = threadIdx.x;
    int wid = t >> 5, lane = t & 31;
    int n0 = blockIdx.x * 256;

    eg[t] = 0.f;
    __syncthreads();

    // phase A: each warp computes gates for its 32 nodes (lane-strided srel gather)
    for (int k = 0; k < 32; k++) {
        int ln = wid * 32 + k;
        int n = n0 + ln;
        if (n >= N_NODES) break;
        int s = g_rs[n], e = g_rs[n + 1];
        float acc = 0.f;
        for (int i = s + lane; i < e; i += 32) acc += g_srel[__ldg(&g_dst[i])];
#pragma unroll
        for (int off = 16; off; off >>= 1) acc += __shfl_xor_sync(0xffffffffu, acc, off);
        if (lane == 0) eg[ln] = expf(g_gate[n] + acc);   // gate logits bounded; shift-free exp safe
    }
    __syncthreads();

    // phase B: weighted pool; 4 groups of 64 threads, each owns 64 nodes
    int col = t & 63, grp = t >> 6;
    float acc = 0.f;
#pragma unroll 4
    for (int k = grp * 64; k < grp * 64 + 64; k++) {
        int n = n0 + k;
        if (n >= N_NODES) break;
        acc += eg[k] * g_z[(size_t)n * 64 + col];
    }
    part[grp][col] = acc;
    __syncthreads();
    if (t < 64) {
        float s4 = part[0][t] + part[1][t] + part[2][t] + part[3][t];
        atomicAdd(&g_pool[t], s4);
    }
    if (t < 32) {
        float sacc = 0.f;
#pragma unroll
        for (int k = t; k < 256; k += 32) sacc += eg[k];
#pragma unroll
        for (int off = 16; off; off >>= 1) sacc += __shfl_xor_sync(0xffffffffu, sacc, off);
        if (t == 0) atomicAdd(&g_scal[1], sacc);
    }
    __threadfence();
    __syncthreads();
    if (t == 0) slast = (atomicAdd(&g_poolcnt, 1) == gridDim.x - 1) ? 1 : 0;
    __syncthreads();
    if (!slast) return;

    // last block: classifier
    if (t < 64) {
        float inv = 1.f / *((volatile float*)&g_scal[1]);
        pooled[t] = *((volatile float*)&g_pool[t]) * inv;
    }
    __syncthreads();
    if (t < 64) {
        float av = __ldg(&b_cls1[t]);
#pragma unroll
        for (int j = 0; j < 64; j++) av += pooled[j] * __ldg(&w_cls1[t * 64 + j]);
        y1s[t] = lrelu(av);
    }
    __syncthreads();
    if (t < 2) {
        float a = __ldg(&b_cls2[t]);
#pragma unroll
        for (int j = 0; j < 64; j++) a += y1s[j] * __ldg(&w_cls2[t * 64 + j]);
        y2s[t] = a;
    }
    __syncthreads();
    if (t == 0) {
        float m = fmaxf(y2s[0], y2s[1]);
        float e0 = expf(y2s[0] - m), e1 = expf(y2s[1] - m);
        out[0] = e0 / (e0 + e1);
        out[1] = e1 / (e0 + e1);
        out[2 + N_EDGES] = expf(__ldg(&log_std[0]));
        g_poolcnt = 0;
    }
}

// ---------------- launch ----------------
extern "C" void kernel_launch(void* const* d_in, const int* in_sizes, int n_in,
                              void* d_out, int out_size) {
    const float* x        = (const float*)d_in[0];
    const int*   row      = (const int*)d_in[1];
    const int*   col      = (const int*)d_in[2];
    const float* w_rel1   = (const float*)d_in[3];
    const float* w_root1  = (const float*)d_in[4];
    const float* b1       = (const float*)d_in[5];
    const float* w_rel_mu = (const float*)d_in[6];
    const float* w_root_mu= (const float*)d_in[7];
    const float* b_mu     = (const float*)d_in[8];
    const float* w_std    = (const float*)d_in[9];
    const float* b_std    = (const float*)d_in[10];
    const float* w_rel_g1 = (const float*)d_in[11];
    const float* w_root_g1= (const float*)d_in[12];
    const float* b_g1     = (const float*)d_in[13];
    const float* w_rel_g2 = (const float*)d_in[14];
    const float* w_root_g2= (const float*)d_in[15];
    const float* b_g2     = (const float*)d_in[16];
    const float* w_cls1   = (const float*)d_in[17];
    const float* b_cls1   = (const float*)d_in[18];
    const float* w_cls2   = (const float*)d_in[19];
    const float* b_cls2   = (const float*)d_in[20];
    const float* log_std  = (const float*)d_in[21];

    float* out       = (float*)d_out;
    float* out_wmu   = out + 2;
    float* out_z     = out + 3 + N_EDGES;
    float* out_zmu   = out_z + (size_t)N_NODES * 64;
    float* out_zstd  = out_zmu + (size_t)N_NODES * 64;

    const int MB = (N_NODES + 127) / 128;
    const int EB = (N_EDGES + 255) / 256;
    const int WB = (N_NODES * 32 + 255) / 256;
    const int NBZ = (N_NODES + 255) / 256;

    const int SM1 = (2 * 128 * 40 * 2 + 2 * 128 * 40 * 2) * 2;  // 81920
    const int SM2 = (2 * 128 * 40 * 2 + 2 * 64 * 40 * 2) * 2;   // 61440

    static cudaStream_t s1 = nullptr;
    static cudaEvent_t ev_root = nullptr, ev_csr = nullptr, ev_h = nullptr,
                       ev_z = nullptr, ev_cos = nullptr;
    if (s1 == nullptr) {
        cudaStreamCreateWithFlags(&s1, cudaStreamNonBlocking);
        cudaEventCreateWithFlags(&ev_root, cudaEventDisableTiming);
        cudaEventCreateWithFlags(&ev_csr, cudaEventDisableTiming);
        cudaEventCreateWithFlags(&ev_h, cudaEventDisableTiming);
        cudaEventCreateWithFlags(&ev_z, cudaEventDisableTiming);
        cudaEventCreateWithFlags(&ev_cos, cudaEventDisableTiming);
        cudaFuncSetAttribute(mma_gemm_kernel<1>, cudaFuncAttributeMaxDynamicSharedMemorySize, SM1);
        cudaFuncSetAttribute(mma_gemm_kernel<2>, cudaFuncAttributeMaxDynamicSharedMemorySize, SM2);
        cudaFuncSetAttribute(mma_gemm_kernel<3>, cudaFuncAttributeMaxDynamicSharedMemorySize, SM2);
        cudaFuncSetAttribute(mma_gemm_kernel<4>, cudaFuncAttributeMaxDynamicSharedMemorySize, SM2);
    }

    // ---- fork 1: CSR build on s1 || gemm1 on main ----
    cudaEventRecord(ev_root, 0);
    cudaStreamWaitEvent(s1, ev_root, 0);

    hist_kernel<<<EB, 256, 0, s1>>>(row);
    bsum_kernel<<<NB_SCAN, 256, 0, s1>>>();
    lscan2_kernel<<<NB_SCAN, 256, 0, s1>>>();
    fill_kernel<<<EB, 256, 0, s1>>>(row, col);
    cudaEventRecord(ev_csr, s1);

    mma_gemm_kernel<1><<<dim3(2, MB), 256, SM1>>>(x, w_rel1, w_root1, b1, nullptr);

    cudaStreamWaitEvent(0, ev_csr, 0);
    gather_h_kernel<<<WB, 256>>>();
    cudaEventRecord(ev_h, 0);

    // std head on s1 (only needs g_h; writes out_zstd)
    cudaStreamWaitEvent(s1, ev_h, 0);
    mma_gemm_kernel<4><<<dim3(1, MB), 256, SM2, s1>>>(nullptr, w_std, nullptr, b_std, out_zstd);

    // layer 2 main (mu heads)
    mma_gemm_kernel<2><<<dim3(2, MB), 256, SM2>>>(nullptr, w_rel_mu, w_root_mu, b_mu, nullptr);
    gather_z_kernel<<<WB, 256>>>();
    cudaEventRecord(ev_z, 0);

    // ---- fork 2: z copies + edge cosine on s1 || gating chain on main ----
    cudaStreamWaitEvent(s1, ev_z, 0);
    copyz_kernel<<<(N_NODES * 64 + 255) / 256, 256, 0, s1>>>(out_z, out_zmu);
    edge_cos_kernel<<<EB, 256, 0, s1>>>(row, col, out_wmu);
    cudaEventRecord(ev_cos, s1);

    mma_gemm_kernel<3><<<dim3(2, MB), 256, SM2>>>(nullptr, w_rel_g1, w_root_g1, b_g1, nullptr);
    gather_g_kernel<<<WB, 256>>>(w_rel_g2, w_root_g2, b_g2);
    pool_final_kernel<<<NBZ, 256>>>(w_cls1, b_cls1, w_cls2, b_cls2, log_std, out);

    cudaStreamWaitEvent(0, ev_cos, 0);
}

// round 16
// speedup vs baseline: 1.0791x; 1.0791x over previous
#include <cuda_runtime.h>
#include <cuda_bf16.h>
#include <math.h>
#include <stdint.h>

#define N_NODES 50000
#define N_EDGES 800000
#define NB_SCAN 196   // ceil(50000 / 256)
// dims: IN=256, EMB1=128, EMB2=64, L1=64

// ---------------- device scratch ----------------
__device__ float g_xr1 [(size_t)N_NODES * 128];
__device__ float g_h   [(size_t)N_NODES * 128];   // root1+b1, then lrelu(h) in-place
__device__ float g_zr  [(size_t)N_NODES * 64];
__device__ float g_zbuf[(size_t)N_NODES * 64];
__device__ float g_z   [(size_t)N_NODES * 64];
__device__ float g_gr  [(size_t)N_NODES * 64];
__device__ float g_gbuf[(size_t)N_NODES * 64];
__device__ float g_srel[N_NODES];
__device__ float g_gate[N_NODES];
__device__ float g_norm[N_NODES];
__device__ float g_pool[64];
__device__ float g_scal[2];
__device__ int g_poolcnt;   // zero-init; reset by last pool block
// CSR  (g_cnt zero-init; lscan2 re-zeroes each call)
__device__ int g_cnt[N_NODES];
__device__ int g_rs[N_NODES + 1];
__device__ int g_fill[N_NODES];
__device__ int g_dst[N_EDGES];
__device__ int g_bsum[NB_SCAN];

__device__ __forceinline__ float lrelu(float v) { return v > 0.f ? v : 0.2f * v; }

// pack two floats -> bf16x2 hi (returned) and bf16x2 lo (out-param)
__device__ __forceinline__ uint32_t packhl(float a, float b, uint32_t& lo) {
    __nv_bfloat162 h2 = __floats2bfloat162_rn(a, b);
    uint32_t hu = *reinterpret_cast<uint32_t*>(&h2);
    float ra = __uint_as_float(hu << 16);
    float rb = __uint_as_float(hu & 0xFFFF0000u);
    __nv_bfloat162 l2 = __floats2bfloat162_rn(a - ra, b - rb);
    lo = *reinterpret_cast<uint32_t*>(&l2);
    return hu;
}
__device__ __forceinline__ void cvt8(const float4& v0, const float4& v1, uint4& hi, uint4& lo) {
    hi.x = packhl(v0.x, v0.y, lo.x);
    hi.y = packhl(v0.z, v0.w, lo.y);
    hi.z = packhl(v1.x, v1.y, lo.z);
    hi.w = packhl(v1.z, v1.w, lo.w);
}

#define MMA_BF16(c0, c1, c2, c3, a0, a1, a2, a3, b0, b1)                          \
    asm volatile("mma.sync.aligned.m16n8k16.row.col.f32.bf16.bf16.f32 "           \
                 "{%0,%1,%2,%3}, {%4,%5,%6,%7}, {%8,%9}, {%0,%1,%2,%3};"          \
                 : "+f"(c0), "+f"(c1), "+f"(c2), "+f"(c3)                         \
                 : "r"(a0), "r"(a1), "r"(a2), "r"(a3), "r"(b0), "r"(b1))

// ---------------- CSR build ----------------
__global__ void hist_kernel(const int* __restrict__ row) {
    int e = blockIdx.x * blockDim.x + threadIdx.x;
    if (e < N_EDGES) atomicAdd(&g_cnt[__ldg(&row[e])], 1);
}

__global__ void bsum_kernel() {
    __shared__ int sm[256];
    int t = threadIdx.x;
    int idx = blockIdx.x * 256 + t;
    sm[t] = (idx < N_NODES) ? g_cnt[idx] : 0;
    __syncthreads();
    for (int s = 128; s > 0; s >>= 1) {
        if (t < s) sm[t] += sm[t + s];
        __syncthreads();
    }
    if (t == 0) g_bsum[blockIdx.x] = sm[0];
    if (blockIdx.x == 0) {
        if (t < 64) g_pool[t] = 0.f;
        if (t == 64) g_scal[1] = 0.f;
    }
}

__global__ void lscan2_kernel() {
    __shared__ int pre[256];
    __shared__ int sm[256];
    int t = threadIdx.x, bid = blockIdx.x;
    pre[t] = (t < bid) ? g_bsum[t] : 0;
    __syncthreads();
    for (int s = 128; s > 0; s >>= 1) {
        if (t < s) pre[t] += pre[t + s];
        __syncthreads();
    }
    int boff = pre[0];
    int idx = bid * 256 + t;
    int v = (idx < N_NODES) ? g_cnt[idx] : 0;
    sm[t] = v;
    __syncthreads();
    for (int off = 1; off < 256; off <<= 1) {
        int u = (t >= off) ? sm[t - off] : 0;
        __syncthreads();
        sm[t] += u;
        __syncthreads();
    }
    if (idx < N_NODES) {
        int r = boff + sm[t] - v;
        g_rs[idx] = r;
        g_fill[idx] = r;
        g_cnt[idx] = 0;
    }
    if (bid == NB_SCAN - 1 && t == 255) g_rs[N_NODES] = boff + sm[255];
}

__global__ void fill_kernel(const int* __restrict__ row, const int* __restrict__ col) {
    int e = blockIdx.x * blockDim.x + threadIdx.x;
    if (e >= N_EDGES) return;
    int pos = atomicAdd(&g_fill[__ldg(&row[e])], 1);
    g_dst[pos] = __ldg(&col[e]);
}

// ------- double-buffered mma.sync bf16 hi/lo GEMM; LDG -> MMA -> STS pipeline -------
// MODE 1: A=x (K=256), BN=128, grid.x=2: bx0 w_rel1 -> g_xr1 ; bx1 w_root1 -> g_h = v + b1
// MODE 2: A=g_h (K=128), BN=64, grid.x=2: bx0 wrm -> g_zr ; bx1 wom -> g_zbuf = v+b_mu
// MODE 3: A=g_z (K=64),  BN=64, grid.x=2: bx0 wrg1 -> g_gr ; bx1 wog1 -> g_gbuf = v+b_g1
// MODE 4: A=g_h (K=128), BN=64, grid.x=1: W0=w_std -> out_extra = exp(tanh(v+b_std))
template <int MODE>
__global__ __launch_bounds__(256)
void mma_gemm_kernel(const float* __restrict__ Ax,
                     const float* __restrict__ W0, const float* __restrict__ W1,
                     const float* __restrict__ bias0,
                     float* __restrict__ out_extra) {
    constexpr int K   = (MODE == 1) ? 256 : (MODE == 3) ? 64 : 128;
    constexpr int BN  = (MODE == 1) ? 128 : 64;
    constexpr int JT  = BN / 16;
    constexpr int NST = K / 32;
    constexpr int AP  = 40;
    constexpr int ASZ = 128 * AP;
    constexpr int BSZ = BN * AP;
    constexpr int BIT = BN / 64;

    extern __shared__ __align__(16) __nv_bfloat16 smArr[];
    __nv_bfloat16* Ah = smArr;
    __nv_bfloat16* Al = Ah + 2 * ASZ;
    __nv_bfloat16* Bh = Al + 2 * ASZ;
    __nv_bfloat16* Bl = Bh + 2 * BSZ;

    const float* A = (MODE == 1) ? Ax : (MODE == 3) ? (const float*)g_z : (const float*)g_h;
    const float* W = (blockIdx.x == 0) ? W0 : W1;

    const int tid = threadIdx.x;
    const int wid = tid >> 5, lane = tid & 31;
    const int wm = wid & 3, wn = wid >> 2;
    const int g = lane >> 2, tq = lane & 3;
    const int row0 = blockIdx.y * 128;
    const int col0 = blockIdx.x * BN;
    const int rm = wm * 32, cn = wn * (BN / 2);
    const int ra = tid >> 2;
    const int ch = (tid & 3) * 8;

    float acc[2][JT][4];
#pragma unroll
    for (int i = 0; i < 2; i++)
#pragma unroll
        for (int j = 0; j < JT; j++)
#pragma unroll
            for (int p = 0; p < 4; p++) acc[i][j][p] = 0.f;

    float4 av[2][2], bv[BIT][2];

    auto ldg_stage = [&](int s) {
        int k0 = s * 32;
#pragma unroll
        for (int it = 0; it < 2; it++) {
            int grow = row0 + ra + it * 64;
            if (grow >= N_NODES) grow = N_NODES - 1;
            const float4* src = (const float4*)&A[(size_t)grow * K + k0 + ch];
            av[it][0] = src[0]; av[it][1] = src[1];
        }
#pragma unroll
        for (int it = 0; it < BIT; it++) {
            const float4* src = (const float4*)&W[(size_t)(ra + it * 64) * K + k0 + ch];
            bv[it][0] = src[0]; bv[it][1] = src[1];
        }
    };
    auto sts_stage = [&](int s) {
        int buf = s & 1;
#pragma unroll
        for (int it = 0; it < 2; it++) {
            uint4 hi, lo;
            cvt8(av[it][0], av[it][1], hi, lo);
            int r = ra + it * 64;
            *(uint4*)&Ah[buf * ASZ + r * AP + ch] = hi;
            *(uint4*)&Al[buf * ASZ + r * AP + ch] = lo;
        }
#pragma unroll
        for (int it = 0; it < BIT; it++) {
            uint4 hi, lo;
            cvt8(bv[it][0], bv[it][1], hi, lo);
            int r = ra + it * 64;
            *(uint4*)&Bh[buf * BSZ + r * AP + ch] = hi;
            *(uint4*)&Bl[buf * BSZ + r * AP + ch] = lo;
        }
    };

    ldg_stage(0);
    sts_stage(0);
    __syncthreads();

    for (int s = 0; s < NST; s++) {
        if (s + 1 < NST) ldg_stage(s + 1);   // LDGs in flight during current MMAs
        const int buf = s & 1;
        const __nv_bfloat16* cAh = Ah + buf * ASZ;
        const __nv_bfloat16* cAl = Al + buf * ASZ;
        const __nv_bfloat16* cBh = Bh + buf * BSZ;
        const __nv_bfloat16* cBl = Bl + buf * BSZ;
#pragma unroll
        for (int ks = 0; ks < 32; ks += 16) {
            uint32_t ah[2][4], al[2][4], bh[JT][2], bl[JT][2];
#pragma unroll
            for (int i = 0; i < 2; i++) {
                int r = rm + i * 16 + g;
                ah[i][0] = *(const uint32_t*)&cAh[r * AP + ks + tq * 2];
                ah[i][1] = *(const uint32_t*)&cAh[(r + 8) * AP + ks + tq * 2];
                ah[i][2] = *(const uint32_t*)&cAh[r * AP + ks + tq * 2 + 8];
                ah[i][3] = *(const uint32_t*)&cAh[(r + 8) * AP + ks + tq * 2 + 8];
                al[i][0] = *(const uint32_t*)&cAl[r * AP + ks + tq * 2];
                al[i][1] = *(const uint32_t*)&cAl[(r + 8) * AP + ks + tq * 2];
                al[i][2] = *(const uint32_t*)&cAl[r * AP + ks + tq * 2 + 8];
                al[i][3] = *(const uint32_t*)&cAl[(r + 8) * AP + ks + tq * 2 + 8];
            }
#pragma unroll
            for (int j = 0; j < JT; j++) {
                int n = cn + j * 8 + g;
                bh[j][0] = *(const uint32_t*)&cBh[n * AP + ks + tq * 2];
                bh[j][1] = *(const uint32_t*)&cBh[n * AP + ks + tq * 2 + 8];
                bl[j][0] = *(const uint32_t*)&cBl[n * AP + ks + tq * 2];
                bl[j][1] = *(const uint32_t*)&cBl[n * AP + ks + tq * 2 + 8];
            }
#pragma unroll
            for (int i = 0; i < 2; i++)
#pragma unroll
                for (int j = 0; j < JT; j++) {
                    MMA_BF16(acc[i][j][0], acc[i][j][1], acc[i][j][2], acc[i][j][3],
                             ah[i][0], ah[i][1], ah[i][2], ah[i][3], bh[j][0], bh[j][1]);
                    MMA_BF16(acc[i][j][0], acc[i][j][1], acc[i][j][2], acc[i][j][3],
                             al[i][0], al[i][1], al[i][2], al[i][3], bh[j][0], bh[j][1]);
                    MMA_BF16(acc[i][j][0], acc[i][j][1], acc[i][j][2], acc[i][j][3],
                             ah[i][0], ah[i][1], ah[i][2], ah[i][3], bl[j][0], bl[j][1]);
                }
        }
        if (s + 1 < NST) {
            sts_stage(s + 1);                // convert + STS after compute
            __syncthreads();
        }
    }

#pragma unroll
    for (int i = 0; i < 2; i++) {
#pragma unroll
        for (int half = 0; half < 2; half++) {
            int m = row0 + rm + i * 16 + g + half * 8;
            if (m >= N_NODES) continue;
#pragma unroll
            for (int j = 0; j < JT; j++) {
                int gcol = col0 + cn + j * 8 + tq * 2;
                float2 v = make_float2(acc[i][j][half * 2], acc[i][j][half * 2 + 1]);
                if (MODE == 1) {
                    if (gcol < 128) {
                        *(float2*)&g_xr1[(size_t)m * 128 + gcol] = v;
                    } else {
                        float2 b = *(const float2*)&bias0[gcol - 128];
                        v.x += b.x; v.y += b.y;
                        *(float2*)&g_h[(size_t)m * 128 + gcol - 128] = v;
                    }
                } else if (MODE == 2) {
                    if (gcol < 64) {
                        *(float2*)&g_zr[(size_t)m * 64 + gcol] = v;
                    } else {
                        float2 b = *(const float2*)&bias0[gcol - 64];
                        v.x += b.x; v.y += b.y;
                        *(float2*)&g_zbuf[(size_t)m * 64 + gcol - 64] = v;
                    }
                } else if (MODE == 3) {
                    if (gcol < 64) {
                        *(float2*)&g_gr[(size_t)m * 64 + gcol] = v;
                    } else {
                        float2 b = *(const float2*)&bias0[gcol - 64];
                        v.x += b.x; v.y += b.y;
                        *(float2*)&g_gbuf[(size_t)m * 64 + gcol - 64] = v;
                    }
                } else {  // MODE 4: std head
                    float2 b = *(const float2*)&bias0[gcol];
                    size_t o = (size_t)m * 64 + gcol;
                    out_extra[o + 0] = expf(tanhf(v.x + b.x));
                    out_extra[o + 1] = expf(tanhf(v.y + b.y));
                }
            }
        }
    }
}

// ---------------- CSR gathers (warp per node, fp32 messages, 4x unrolled) ----------------
__global__ void gather_h_kernel() {
    int gw = (blockIdx.x * blockDim.x + threadIdx.x) >> 5;
    int lane = threadIdx.x & 31;
    if (gw >= N_NODES) return;
    int s = g_rs[gw], e = g_rs[gw + 1];
    float4 acc = make_float4(0.f, 0.f, 0.f, 0.f);
    int i = s;
    for (; i + 4 <= e; i += 4) {
        int c0 = __ldg(&g_dst[i]),     c1 = __ldg(&g_dst[i + 1]);
        int c2 = __ldg(&g_dst[i + 2]), c3 = __ldg(&g_dst[i + 3]);
        float4 v0 = *(const float4*)&g_xr1[(size_t)c0 * 128 + lane * 4];
        float4 v1 = *(const float4*)&g_xr1[(size_t)c1 * 128 + lane * 4];
        float4 v2 = *(const float4*)&g_xr1[(size_t)c2 * 128 + lane * 4];
        float4 v3 = *(const float4*)&g_xr1[(size_t)c3 * 128 + lane * 4];
        acc.x += v0.x + v1.x + v2.x + v3.x;
        acc.y += v0.y + v1.y + v2.y + v3.y;
        acc.z += v0.z + v1.z + v2.z + v3.z;
        acc.w += v0.w + v1.w + v2.w + v3.w;
    }
    for (; i < e; i++) {
        int c = __ldg(&g_dst[i]);
        float4 v = *(const float4*)&g_xr1[(size_t)c * 128 + lane * 4];
        acc.x += v.x; acc.y += v.y; acc.z += v.z; acc.w += v.w;
    }
    size_t o = (size_t)gw * 128 + lane * 4;
    float4 h = *(const float4*)&g_h[o];
    h.x = lrelu(h.x + acc.x); h.y = lrelu(h.y + acc.y);
    h.z = lrelu(h.z + acc.z); h.w = lrelu(h.w + acc.w);
    *(float4*)&g_h[o] = h;
}

__global__ void gather_z_kernel() {
    int gw = (blockIdx.x * blockDim.x + threadIdx.x) >> 5;
    int lane = threadIdx.x & 31;
    if (gw >= N_NODES) return;
    int s = g_rs[gw], e = g_rs[gw + 1];
    float a0 = 0.f, a1 = 0.f;
    int i = s;
    for (; i + 4 <= e; i += 4) {
        int c0 = __ldg(&g_dst[i]),     c1 = __ldg(&g_dst[i + 1]);
        int c2 = __ldg(&g_dst[i + 2]), c3 = __ldg(&g_dst[i + 3]);
        float2 v0 = *(const float2*)&g_zr[(size_t)c0 * 64 + lane * 2];
        float2 v1 = *(const float2*)&g_zr[(size_t)c1 * 64 + lane * 2];
        float2 v2 = *(const float2*)&g_zr[(size_t)c2 * 64 + lane * 2];
        float2 v3 = *(const float2*)&g_zr[(size_t)c3 * 64 + lane * 2];
        a0 += v0.x + v1.x + v2.x + v3.x;
        a1 += v0.y + v1.y + v2.y + v3.y;
    }
    for (; i < e; i++) {
        int c = __ldg(&g_dst[i]);
        float2 v = *(const float2*)&g_zr[(size_t)c * 64 + lane * 2];
        a0 += v.x; a1 += v.y;
    }
    size_t o = (size_t)gw * 64 + lane * 2;
    float2 zb = *(const float2*)&g_zbuf[o];
    float z0 = tanhf(zb.x + a0), z1 = tanhf(zb.y + a1);
    *(float2*)&g_z[o] = make_float2(z0, z1);
    float ss = z0 * z0 + z1 * z1;
#pragma unroll
    for (int off = 16; off; off >>= 1) ss += __shfl_xor_sync(0xffffffffu, ss, off);
    if (lane == 0) g_norm[gw] = fmaxf(sqrtf(ss), 1e-8f);
}

// z -> out_z, out_zmu (runs on side stream)
__global__ void copyz_kernel(float* __restrict__ out_z, float* __restrict__ out_zmu) {
    int i = blockIdx.x * blockDim.x + threadIdx.x;
    if (i >= N_NODES * 64) return;
    float v = g_z[i];
    out_z[i] = v;
    out_zmu[i] = v;
}

__global__ void gather_g_kernel(const float* __restrict__ wrel2, const float* __restrict__ wroot2,
                                const float* __restrict__ bg2) {
    int gw = (blockIdx.x * blockDim.x + threadIdx.x) >> 5;
    int lane = threadIdx.x & 31;
    if (gw >= N_NODES) return;
    int s = g_rs[gw], e = g_rs[gw + 1];
    float a0 = 0.f, a1 = 0.f;
    int i = s;
    for (; i + 4 <= e; i += 4) {
        int c0 = __ldg(&g_dst[i]),     c1 = __ldg(&g_dst[i + 1]);
        int c2 = __ldg(&g_dst[i + 2]), c3 = __ldg(&g_dst[i + 3]);
        float2 v0 = *(const float2*)&g_gr[(size_t)c0 * 64 + lane * 2];
        float2 v1 = *(const float2*)&g_gr[(size_t)c1 * 64 + lane * 2];
        float2 v2 = *(const float2*)&g_gr[(size_t)c2 * 64 + lane * 2];
        float2 v3 = *(const float2*)&g_gr[(size_t)c3 * 64 + lane * 2];
        a0 += v0.x + v1.x + v2.x + v3.x;
        a1 += v0.y + v1.y + v2.y + v3.y;
    }
    for (; i < e; i++) {
        int c = __ldg(&g_dst[i]);
        float2 v = *(const float2*)&g_gr[(size_t)c * 64 + lane * 2];
        a0 += v.x; a1 += v.y;
    }
    size_t o = (size_t)gw * 64 + lane * 2;
    float2 gb = *(const float2*)&g_gbuf[o];
    float g0 = lrelu(gb.x + a0), g1 = lrelu(gb.y + a1);
    float s0 = g0 * __ldg(&wrel2[lane * 2]) + g1 * __ldg(&wrel2[lane * 2 + 1]);
    float s1 = g0 * __ldg(&wroot2[lane * 2]) + g1 * __ldg(&wroot2[lane * 2 + 1]);
#pragma unroll
    for (int off = 16; off; off >>= 1) {
        s0 += __shfl_xor_sync(0xffffffffu, s0, off);
        s1 += __shfl_xor_sync(0xffffffffu, s1, off);
    }
    if (lane == 0) {
        g_srel[gw] = s0;
        g_gate[gw] = s1 + __ldg(&bg2[0]);
    }
}

__global__ void gather_gate_kernel() {
    int gw = (blockIdx.x * blockDim.x + threadIdx.x) >> 5;
    int lane = threadIdx.x & 31;
    if (gw >= N_NODES) return;
    int s = g_rs[gw], e = g_rs[gw + 1];
    float acc = 0.f;
    for (int i = s + lane; i < e; i += 32) acc += g_srel[__ldg(&g_dst[i])];
#pragma unroll
    for (int off = 16; off; off >>= 1) acc += __shfl_xor_sync(0xffffffffu, acc, off);
    if (lane == 0) g_gate[gw] += acc;
}

// ---------------- per-edge cosine similarity ----------------
__global__ void edge_cos_kernel(const int* __restrict__ row, const int* __restrict__ col,
                                float* __restrict__ wmu) {
    int e = blockIdx.x * blockDim.x + threadIdx.x;
    if (e >= N_EDGES) return;
    int r = __ldg(&row[e]);
    int c = __ldg(&col[e]);
    const float4* a = (const float4*)&g_z[(size_t)r * 64];
    const float4* b = (const float4*)&g_z[(size_t)c * 64];
    float acc = 0.f;
#pragma unroll
    for (int i = 0; i < 16; i++) {
        float4 u = __ldg(a + i), v = __ldg(b + i);
        acc += u.x * v.x + u.y * v.y + u.z * v.z + u.w * v.w;
    }
    wmu[e] = acc / (g_norm[r] * g_norm[c]);
}

// ---------------- fused: sum exp + weighted pool + classifier (last block) ----------------
// 128 threads: two 64-thread groups each handle 128 of the block's 256 nodes.
__global__ __launch_bounds__(128)
void pool_final_kernel(const float* __restrict__ w_cls1, const float* __restrict__ b_cls1,
                       const float* __restrict__ w_cls2, const float* __restrict__ b_cls2,
                       const float* __restrict__ log_std, float* __restrict__ out) {
    __shared__ float part[2][64];
    __shared__ float psum[2];
    __shared__ float pooled[64], y1s[64], y2s[2];
    __shared__ int slast;
    int t = threadIdx.x;          // 0..127
    int col = t & 63, grp = t >> 6;
    int n0 = blockIdx.x * 256 + grp * 128;
    int n1 = n0 + 128; if (n1 > N_NODES) n1 = N_NODES;
    float acc = 0.f, sacc = 0.f;
    for (int n = n0; n < n1; n++) {
        float w = expf(g_gate[n]);   // bounded logits; shift-free exp safe
        acc += w * g_z[(size_t)n * 64 + col];
        if (col == 0) sacc += w;
    }
    part[grp][col] = acc;
    if (col == 0) psum[grp] = sacc;
    __syncthreads();
    if (t < 64) atomicAdd(&g_pool[t], part[0][t] + part[1][t]);
    if (t == 0) atomicAdd(&g_scal[1], psum[0] + psum[1]);
    __threadfence();
    __syncthreads();
    if (t == 0) slast = (atomicAdd(&g_poolcnt, 1) == gridDim.x - 1) ? 1 : 0;
    __syncthreads();
    if (!slast) return;

    if (t < 64) {
        float inv = 1.f / *((volatile float*)&g_scal[1]);
        pooled[t] = *((volatile float*)&g_pool[t]) * inv;
    }
    __syncthreads();
    if (t < 64) {
        float av = __ldg(&b_cls1[t]);
#pragma unroll
        for (int j = 0; j < 64; j++) av += pooled[j] * __ldg(&w_cls1[t * 64 + j]);
        y1s[t] = lrelu(av);
    }
    __syncthreads();
    if (t < 2) {
        float a = __ldg(&b_cls2[t]);
#pragma unroll
        for (int j = 0; j < 64; j++) a += y1s[j] * __ldg(&w_cls2[t * 64 + j]);
        y2s[t] = a;
    }
    __syncthreads();
    if (t == 0) {
        float m = fmaxf(y2s[0], y2s[1]);
        float e0 = expf(y2s[0] - m), e1 = expf(y2s[1] - m);
        out[0] = e0 / (e0 + e1);
        out[1] = e1 / (e0 + e1);
        out[2 + N_EDGES] = expf(__ldg(&log_std[0]));
        g_poolcnt = 0;
    }
}

// ---------------- launch ----------------
extern "C" void kernel_launch(void* const* d_in, const int* in_sizes, int n_in,
                              void* d_out, int out_size) {
    const float* x        = (const float*)d_in[0];
    const int*   row      = (const int*)d_in[1];
    const int*   col      = (const int*)d_in[2];
    const float* w_rel1   = (const float*)d_in[3];
    const float* w_root1  = (const float*)d_in[4];
    const float* b1       = (const float*)d_in[5];
    const float* w_rel_mu = (const float*)d_in[6];
    const float* w_root_mu= (const float*)d_in[7];
    const float* b_mu     = (const float*)d_in[8];
    const float* w_std    = (const float*)d_in[9];
    const float* b_std    = (const float*)d_in[10];
    const float* w_rel_g1 = (const float*)d_in[11];
    const float* w_root_g1= (const float*)d_in[12];
    const float* b_g1     = (const float*)d_in[13];
    const float* w_rel_g2 = (const float*)d_in[14];
    const float* w_root_g2= (const float*)d_in[15];
    const float* b_g2     = (const float*)d_in[16];
    const float* w_cls1   = (const float*)d_in[17];
    const float* b_cls1   = (const float*)d_in[18];
    const float* w_cls2   = (const float*)d_in[19];
    const float* b_cls2   = (const float*)d_in[20];
    const float* log_std  = (const float*)d_in[21];

    float* out       = (float*)d_out;
    float* out_wmu   = out + 2;
    float* out_z     = out + 3 + N_EDGES;
    float* out_zmu   = out_z + (size_t)N_NODES * 64;
    float* out_zstd  = out_zmu + (size_t)N_NODES * 64;

    const int MB = (N_NODES + 127) / 128;
    const int EB = (N_EDGES + 255) / 256;
    const int WB = (N_NODES * 32 + 255) / 256;
    const int NBZ = (N_NODES + 255) / 256;

    const int SM1 = (2 * 128 * 40 * 2 + 2 * 128 * 40 * 2) * 2;  // 81920
    const int SM2 = (2 * 128 * 40 * 2 + 2 * 64 * 40 * 2) * 2;   // 61440

    static cudaStream_t s1 = nullptr;
    static cudaEvent_t ev_root = nullptr, ev_csr = nullptr, ev_h = nullptr,
                       ev_z = nullptr, ev_cos = nullptr;
    if (s1 == nullptr) {
        cudaStreamCreateWithFlags(&s1, cudaStreamNonBlocking);
        cudaEventCreateWithFlags(&ev_root, cudaEventDisableTiming);
        cudaEventCreateWithFlags(&ev_csr, cudaEventDisableTiming);
        cudaEventCreateWithFlags(&ev_h, cudaEventDisableTiming);
        cudaEventCreateWithFlags(&ev_z, cudaEventDisableTiming);
        cudaEventCreateWithFlags(&ev_cos, cudaEventDisableTiming);
        cudaFuncSetAttribute(mma_gemm_kernel<1>, cudaFuncAttributeMaxDynamicSharedMemorySize, SM1);
        cudaFuncSetAttribute(mma_gemm_kernel<2>, cudaFuncAttributeMaxDynamicSharedMemorySize, SM2);
        cudaFuncSetAttribute(mma_gemm_kernel<3>, cudaFuncAttributeMaxDynamicSharedMemorySize, SM2);
        cudaFuncSetAttribute(mma_gemm_kernel<4>, cudaFuncAttributeMaxDynamicSharedMemorySize, SM2);
    }

    // ---- fork 1: CSR build on s1 || gemm1 on main ----
    cudaEventRecord(ev_root, 0);
    cudaStreamWaitEvent(s1, ev_root, 0);

    hist_kernel<<<EB, 256, 0, s1>>>(row);
    bsum_kernel<<<NB_SCAN, 256, 0, s1>>>();
    lscan2_kernel<<<NB_SCAN, 256, 0, s1>>>();
    fill_kernel<<<EB, 256, 0, s1>>>(row, col);
    cudaEventRecord(ev_csr, s1);

    mma_gemm_kernel<1><<<dim3(2, MB), 256, SM1>>>(x, w_rel1, w_root1, b1, nullptr);

    cudaStreamWaitEvent(0, ev_csr, 0);
    gather_h_kernel<<<WB, 256>>>();
    cudaEventRecord(ev_h, 0);

    // std head on s1 (only needs g_h; writes out_zstd)
    cudaStreamWaitEvent(s1, ev_h, 0);
    mma_gemm_kernel<4><<<dim3(1, MB), 256, SM2, s1>>>(nullptr, w_std, nullptr, b_std, out_zstd);

    // layer 2 main (mu heads)
    mma_gemm_kernel<2><<<dim3(2, MB), 256, SM2>>>(nullptr, w_rel_mu, w_root_mu, b_mu, nullptr);
    gather_z_kernel<<<WB, 256>>>();
    cudaEventRecord(ev_z, 0);

    // ---- fork 2: z copies + edge cosine on s1 || gating chain on main ----
    cudaStreamWaitEvent(s1, ev_z, 0);
    copyz_kernel<<<(N_NODES * 64 + 255) / 256, 256, 0, s1>>>(out_z, out_zmu);
    edge_cos_kernel<<<EB, 256, 0, s1>>>(row, col, out_wmu);
    cudaEventRecord(ev_cos, s1);

    mma_gemm_kernel<3><<<dim3(2, MB), 256, SM2>>>(nullptr, w_rel_g1, w_root_g1, b_g1, nullptr);
    gather_g_kernel<<<WB, 256>>>(w_rel_g2, w_root_g2, b_g2);
    gather_gate_kernel<<<WB, 256>>>();
    pool_final_kernel<<<NBZ, 128>>>(w_cls1, b_cls1, w_cls2, b_cls2, log_std, out);

    cudaStreamWaitEvent(0, ev_cos, 0);
}

// round 17
// speedup vs baseline: 1.0867x; 1.0071x over previous
#include <cuda_runtime.h>
#include <cuda_bf16.h>
#include <math.h>
#include <stdint.h>

#define N_NODES 50000
#define N_EDGES 800000
#define NB_SCAN 196   // ceil(50000 / 256)
// dims: IN=256, EMB1=128, EMB2=64, L1=64

// ---------------- device scratch ----------------
__device__ float g_xr1 [(size_t)N_NODES * 128];
__device__ float g_h   [(size_t)N_NODES * 128];   // root1+b1, then lrelu(h) in-place
__device__ float g_zr  [(size_t)N_NODES * 64];
__device__ float g_zbuf[(size_t)N_NODES * 64];
__device__ float g_z   [(size_t)N_NODES * 64];
__device__ float g_gr  [(size_t)N_NODES * 64];
__device__ float g_gbuf[(size_t)N_NODES * 64];
__device__ float g_srel[N_NODES];
__device__ float g_gate[N_NODES];
__device__ float g_norm[N_NODES];
__device__ float g_pool[64];
__device__ float g_scal[2];
__device__ int g_poolcnt;   // zero-init; reset by last pool block
// CSR  (g_cnt zero-init; lscan2 re-zeroes each call)
__device__ int g_cnt[N_NODES];
__device__ int g_rs[N_NODES + 1];
__device__ int g_fill[N_NODES];
__device__ int g_dst[N_EDGES];
__device__ int g_bsum[NB_SCAN];

__device__ __forceinline__ float lrelu(float v) { return v > 0.f ? v : 0.2f * v; }

// pack two floats -> bf16x2 hi (returned) and bf16x2 lo (out-param)
__device__ __forceinline__ uint32_t packhl(float a, float b, uint32_t& lo) {
    __nv_bfloat162 h2 = __floats2bfloat162_rn(a, b);
    uint32_t hu = *reinterpret_cast<uint32_t*>(&h2);
    float ra = __uint_as_float(hu << 16);
    float rb = __uint_as_float(hu & 0xFFFF0000u);
    __nv_bfloat162 l2 = __floats2bfloat162_rn(a - ra, b - rb);
    lo = *reinterpret_cast<uint32_t*>(&l2);
    return hu;
}
__device__ __forceinline__ void cvt8(const float4& v0, const float4& v1, uint4& hi, uint4& lo) {
    hi.x = packhl(v0.x, v0.y, lo.x);
    hi.y = packhl(v0.z, v0.w, lo.y);
    hi.z = packhl(v1.x, v1.y, lo.z);
    hi.w = packhl(v1.z, v1.w, lo.w);
}

#define MMA_BF16(c0, c1, c2, c3, a0, a1, a2, a3, b0, b1)                          \
    asm volatile("mma.sync.aligned.m16n8k16.row.col.f32.bf16.bf16.f32 "           \
                 "{%0,%1,%2,%3}, {%4,%5,%6,%7}, {%8,%9}, {%0,%1,%2,%3};"          \
                 : "+f"(c0), "+f"(c1), "+f"(c2), "+f"(c3)                         \
                 : "r"(a0), "r"(a1), "r"(a2), "r"(a3), "r"(b0), "r"(b1))

// ---------------- CSR build ----------------
__global__ void hist_kernel(const int* __restrict__ row) {
    int e = blockIdx.x * blockDim.x + threadIdx.x;
    if (e < N_EDGES) atomicAdd(&g_cnt[__ldg(&row[e])], 1);
}

__global__ void bsum_kernel() {
    __shared__ int sm[256];
    int t = threadIdx.x;
    int idx = blockIdx.x * 256 + t;
    sm[t] = (idx < N_NODES) ? g_cnt[idx] : 0;
    __syncthreads();
    for (int s = 128; s > 0; s >>= 1) {
        if (t < s) sm[t] += sm[t + s];
        __syncthreads();
    }
    if (t == 0) g_bsum[blockIdx.x] = sm[0];
    if (blockIdx.x == 0) {
        if (t < 64) g_pool[t] = 0.f;
        if (t == 64) g_scal[1] = 0.f;
    }
}

__global__ void lscan2_kernel() {
    __shared__ int pre[256];
    __shared__ int sm[256];
    int t = threadIdx.x, bid = blockIdx.x;
    pre[t] = (t < bid) ? g_bsum[t] : 0;
    __syncthreads();
    for (int s = 128; s > 0; s >>= 1) {
        if (t < s) pre[t] += pre[t + s];
        __syncthreads();
    }
    int boff = pre[0];
    int idx = bid * 256 + t;
    int v = (idx < N_NODES) ? g_cnt[idx] : 0;
    sm[t] = v;
    __syncthreads();
    for (int off = 1; off < 256; off <<= 1) {
        int u = (t >= off) ? sm[t - off] : 0;
        __syncthreads();
        sm[t] += u;
        __syncthreads();
    }
    if (idx < N_NODES) {
        int r = boff + sm[t] - v;
        g_rs[idx] = r;
        g_fill[idx] = r;
        g_cnt[idx] = 0;
    }
    if (bid == NB_SCAN - 1 && t == 255) g_rs[N_NODES] = boff + sm[255];
}

__global__ void fill_kernel(const int* __restrict__ row, const int* __restrict__ col) {
    int e = blockIdx.x * blockDim.x + threadIdx.x;
    if (e >= N_EDGES) return;
    int pos = atomicAdd(&g_fill[__ldg(&row[e])], 1);
    g_dst[pos] = __ldg(&col[e]);
}

// ------- double-buffered mma.sync bf16 hi/lo GEMM; LDG -> MMA -> STS pipeline -------
// MODE 1: A=x (K=256), BN=128, grid.x=2: bx0 w_rel1 -> g_xr1 ; bx1 w_root1 -> g_h = v + b1
// MODE 2: A=g_h (K=128), BN=64, grid.x=2: bx0 wrm -> g_zr ; bx1 wom -> g_zbuf = v+b_mu
// MODE 3: A=g_z (K=64),  BN=64, grid.x=2: bx0 wrg1 -> g_gr ; bx1 wog1 -> g_gbuf = v+b_g1
// MODE 4: A=g_h (K=128), BN=64, grid.x=1: W0=w_std -> out_extra = exp(tanh(v+b_std))
template <int MODE>
__global__ __launch_bounds__(256)
void mma_gemm_kernel(const float* __restrict__ Ax,
                     const float* __restrict__ W0, const float* __restrict__ W1,
                     const float* __restrict__ bias0,
                     float* __restrict__ out_extra) {
    constexpr int K   = (MODE == 1) ? 256 : (MODE == 3) ? 64 : 128;
    constexpr int BN  = (MODE == 1) ? 128 : 64;
    constexpr int JT  = BN / 16;
    constexpr int NST = K / 32;
    constexpr int AP  = 40;
    constexpr int ASZ = 128 * AP;
    constexpr int BSZ = BN * AP;
    constexpr int BIT = BN / 64;

    extern __shared__ __align__(16) __nv_bfloat16 smArr[];
    __nv_bfloat16* Ah = smArr;
    __nv_bfloat16* Al = Ah + 2 * ASZ;
    __nv_bfloat16* Bh = Al + 2 * ASZ;
    __nv_bfloat16* Bl = Bh + 2 * BSZ;

    const float* A = (MODE == 1) ? Ax : (MODE == 3) ? (const float*)g_z : (const float*)g_h;
    const float* W = (blockIdx.x == 0) ? W0 : W1;

    const int tid = threadIdx.x;
    const int wid = tid >> 5, lane = tid & 31;
    const int wm = wid & 3, wn = wid >> 2;
    const int g = lane >> 2, tq = lane & 3;
    const int row0 = blockIdx.y * 128;
    const int col0 = blockIdx.x * BN;
    const int rm = wm * 32, cn = wn * (BN / 2);
    const int ra = tid >> 2;
    const int ch = (tid & 3) * 8;

    float acc[2][JT][4];
#pragma unroll
    for (int i = 0; i < 2; i++)
#pragma unroll
        for (int j = 0; j < JT; j++)
#pragma unroll
            for (int p = 0; p < 4; p++) acc[i][j][p] = 0.f;

    float4 av[2][2], bv[BIT][2];

    auto ldg_stage = [&](int s) {
        int k0 = s * 32;
#pragma unroll
        for (int it = 0; it < 2; it++) {
            int grow = row0 + ra + it * 64;
            if (grow >= N_NODES) grow = N_NODES - 1;
            const float4* src = (const float4*)&A[(size_t)grow * K + k0 + ch];
            av[it][0] = src[0]; av[it][1] = src[1];
        }
#pragma unroll
        for (int it = 0; it < BIT; it++) {
            const float4* src = (const float4*)&W[(size_t)(ra + it * 64) * K + k0 + ch];
            bv[it][0] = src[0]; bv[it][1] = src[1];
        }
    };
    auto sts_stage = [&](int s) {
        int buf = s & 1;
#pragma unroll
        for (int it = 0; it < 2; it++) {
            uint4 hi, lo;
            cvt8(av[it][0], av[it][1], hi, lo);
            int r = ra + it * 64;
            *(uint4*)&Ah[buf * ASZ + r * AP + ch] = hi;
            *(uint4*)&Al[buf * ASZ + r * AP + ch] = lo;
        }
#pragma unroll
        for (int it = 0; it < BIT; it++) {
            uint4 hi, lo;
            cvt8(bv[it][0], bv[it][1], hi, lo);
            int r = ra + it * 64;
            *(uint4*)&Bh[buf * BSZ + r * AP + ch] = hi;
            *(uint4*)&Bl[buf * BSZ + r * AP + ch] = lo;
        }
    };

    ldg_stage(0);
    sts_stage(0);
    __syncthreads();

    for (int s = 0; s < NST; s++) {
        if (s + 1 < NST) ldg_stage(s + 1);   // LDGs in flight during current MMAs
        const int buf = s & 1;
        const __nv_bfloat16* cAh = Ah + buf * ASZ;
        const __nv_bfloat16* cAl = Al + buf * ASZ;
        const __nv_bfloat16* cBh = Bh + buf * BSZ;
        const __nv_bfloat16* cBl = Bl + buf * BSZ;
#pragma unroll
        for (int ks = 0; ks < 32; ks += 16) {
            uint32_t ah[2][4], al[2][4], bh[JT][2], bl[JT][2];
#pragma unroll
            for (int i = 0; i < 2; i++) {
                int r = rm + i * 16 + g;
                ah[i][0] = *(const uint32_t*)&cAh[r * AP + ks + tq * 2];
                ah[i][1] = *(const uint32_t*)&cAh[(r + 8) * AP + ks + tq * 2];
                ah[i][2] = *(const uint32_t*)&cAh[r * AP + ks + tq * 2 + 8];
                ah[i][3] = *(const uint32_t*)&cAh[(r + 8) * AP + ks + tq * 2 + 8];
                al[i][0] = *(const uint32_t*)&cAl[r * AP + ks + tq * 2];
                al[i][1] = *(const uint32_t*)&cAl[(r + 8) * AP + ks + tq * 2];
                al[i][2] = *(const uint32_t*)&cAl[r * AP + ks + tq * 2 + 8];
                al[i][3] = *(const uint32_t*)&cAl[(r + 8) * AP + ks + tq * 2 + 8];
            }
#pragma unroll
            for (int j = 0; j < JT; j++) {
                int n = cn + j * 8 + g;
                bh[j][0] = *(const uint32_t*)&cBh[n * AP + ks + tq * 2];
                bh[j][1] = *(const uint32_t*)&cBh[n * AP + ks + tq * 2 + 8];
                bl[j][0] = *(const uint32_t*)&cBl[n * AP + ks + tq * 2];
                bl[j][1] = *(const uint32_t*)&cBl[n * AP + ks + tq * 2 + 8];
            }
#pragma unroll
            for (int i = 0; i < 2; i++)
#pragma unroll
                for (int j = 0; j < JT; j++) {
                    MMA_BF16(acc[i][j][0], acc[i][j][1], acc[i][j][2], acc[i][j][3],
                             ah[i][0], ah[i][1], ah[i][2], ah[i][3], bh[j][0], bh[j][1]);
                    MMA_BF16(acc[i][j][0], acc[i][j][1], acc[i][j][2], acc[i][j][3],
                             al[i][0], al[i][1], al[i][2], al[i][3], bh[j][0], bh[j][1]);
                    MMA_BF16(acc[i][j][0], acc[i][j][1], acc[i][j][2], acc[i][j][3],
                             ah[i][0], ah[i][1], ah[i][2], ah[i][3], bl[j][0], bl[j][1]);
                }
        }
        if (s + 1 < NST) {
            sts_stage(s + 1);                // convert + STS after compute
            __syncthreads();
        }
    }

#pragma unroll
    for (int i = 0; i < 2; i++) {
#pragma unroll
        for (int half = 0; half < 2; half++) {
            int m = row0 + rm + i * 16 + g + half * 8;
            if (m >= N_NODES) continue;
#pragma unroll
            for (int j = 0; j < JT; j++) {
                int gcol = col0 + cn + j * 8 + tq * 2;
                float2 v = make_float2(acc[i][j][half * 2], acc[i][j][half * 2 + 1]);
                if (MODE == 1) {
                    if (gcol < 128) {
                        *(float2*)&g_xr1[(size_t)m * 128 + gcol] = v;
                    } else {
                        float2 b = *(const float2*)&bias0[gcol - 128];
                        v.x += b.x; v.y += b.y;
                        *(float2*)&g_h[(size_t)m * 128 + gcol - 128] = v;
                    }
                } else if (MODE == 2) {
                    if (gcol < 64) {
                        *(float2*)&g_zr[(size_t)m * 64 + gcol] = v;
                    } else {
                        float2 b = *(const float2*)&bias0[gcol - 64];
                        v.x += b.x; v.y += b.y;
                        *(float2*)&g_zbuf[(size_t)m * 64 + gcol - 64] = v;
                    }
                } else if (MODE == 3) {
                    if (gcol < 64) {
                        *(float2*)&g_gr[(size_t)m * 64 + gcol] = v;
                    } else {
                        float2 b = *(const float2*)&bias0[gcol - 64];
                        v.x += b.x; v.y += b.y;
                        *(float2*)&g_gbuf[(size_t)m * 64 + gcol - 64] = v;
                    }
                } else {  // MODE 4: std head
                    float2 b = *(const float2*)&bias0[gcol];
                    size_t o = (size_t)m * 64 + gcol;
                    out_extra[o + 0] = expf(tanhf(v.x + b.x));
                    out_extra[o + 1] = expf(tanhf(v.y + b.y));
                }
            }
        }
    }
}

// ---------------- CSR gathers (warp per node, fp32 messages, 4x unrolled) ----------------
__global__ void gather_h_kernel() {
    int gw = (blockIdx.x * blockDim.x + threadIdx.x) >> 5;
    int lane = threadIdx.x & 31;
    if (gw >= N_NODES) return;
    int s = g_rs[gw], e = g_rs[gw + 1];
    float4 acc = make_float4(0.f, 0.f, 0.f, 0.f);
    int i = s;
    for (; i + 4 <= e; i += 4) {
        int c0 = __ldg(&g_dst[i]),     c1 = __ldg(&g_dst[i + 1]);
        int c2 = __ldg(&g_dst[i + 2]), c3 = __ldg(&g_dst[i + 3]);
        float4 v0 = *(const float4*)&g_xr1[(size_t)c0 * 128 + lane * 4];
        float4 v1 = *(const float4*)&g_xr1[(size_t)c1 * 128 + lane * 4];
        float4 v2 = *(const float4*)&g_xr1[(size_t)c2 * 128 + lane * 4];
        float4 v3 = *(const float4*)&g_xr1[(size_t)c3 * 128 + lane * 4];
        acc.x += v0.x + v1.x + v2.x + v3.x;
        acc.y += v0.y + v1.y + v2.y + v3.y;
        acc.z += v0.z + v1.z + v2.z + v3.z;
        acc.w += v0.w + v1.w + v2.w + v3.w;
    }
    for (; i < e; i++) {
        int c = __ldg(&g_dst[i]);
        float4 v = *(const float4*)&g_xr1[(size_t)c * 128 + lane * 4];
        acc.x += v.x; acc.y += v.y; acc.z += v.z; acc.w += v.w;
    }
    size_t o = (size_t)gw * 128 + lane * 4;
    float4 h = *(const float4*)&g_h[o];
    h.x = lrelu(h.x + acc.x); h.y = lrelu(h.y + acc.y);
    h.z = lrelu(h.z + acc.z); h.w = lrelu(h.w + acc.w);
    *(float4*)&g_h[o] = h;
}

__global__ void gather_z_kernel() {
    int gw = (blockIdx.x * blockDim.x + threadIdx.x) >> 5;
    int lane = threadIdx.x & 31;
    if (gw >= N_NODES) return;
    int s = g_rs[gw], e = g_rs[gw + 1];
    float a0 = 0.f, a1 = 0.f;
    int i = s;
    for (; i + 4 <= e; i += 4) {
        int c0 = __ldg(&g_dst[i]),     c1 = __ldg(&g_dst[i + 1]);
        int c2 = __ldg(&g_dst[i + 2]), c3 = __ldg(&g_dst[i + 3]);
        float2 v0 = *(const float2*)&g_zr[(size_t)c0 * 64 + lane * 2];
        float2 v1 = *(const float2*)&g_zr[(size_t)c1 * 64 + lane * 2];
        float2 v2 = *(const float2*)&g_zr[(size_t)c2 * 64 + lane * 2];
        float2 v3 = *(const float2*)&g_zr[(size_t)c3 * 64 + lane * 2];
        a0 += v0.x + v1.x + v2.x + v3.x;
        a1 += v0.y + v1.y + v2.y + v3.y;
    }
    for (; i < e; i++) {
        int c = __ldg(&g_dst[i]);
        float2 v = *(const float2*)&g_zr[(size_t)c * 64 + lane * 2];
        a0 += v.x; a1 += v.y;
    }
    size_t o = (size_t)gw * 64 + lane * 2;
    float2 zb = *(const float2*)&g_zbuf[o];
    float z0 = tanhf(zb.x + a0), z1 = tanhf(zb.y + a1);
    *(float2*)&g_z[o] = make_float2(z0, z1);
    float ss = z0 * z0 + z1 * z1;
#pragma unroll
    for (int off = 16; off; off >>= 1) ss += __shfl_xor_sync(0xffffffffu, ss, off);
    if (lane == 0) g_norm[gw] = fmaxf(sqrtf(ss), 1e-8f);
}

// z -> out_z, out_zmu (runs on side stream)
__global__ void copyz_kernel(float* __restrict__ out_z, float* __restrict__ out_zmu) {
    int i = blockIdx.x * blockDim.x + threadIdx.x;
    if (i >= N_NODES * 64) return;
    float v = g_z[i];
    out_z[i] = v;
    out_zmu[i] = v;
}

__global__ void gather_g_kernel(const float* __restrict__ wrel2, const float* __restrict__ wroot2,
                                const float* __restrict__ bg2) {
    int gw = (blockIdx.x * blockDim.x + threadIdx.x) >> 5;
    int lane = threadIdx.x & 31;
    if (gw >= N_NODES) return;
    int s = g_rs[gw], e = g_rs[gw + 1];
    float a0 = 0.f, a1 = 0.f;
    int i = s;
    for (; i + 4 <= e; i += 4) {
        int c0 = __ldg(&g_dst[i]),     c1 = __ldg(&g_dst[i + 1]);
        int c2 = __ldg(&g_dst[i + 2]), c3 = __ldg(&g_dst[i + 3]);
        float2 v0 = *(const float2*)&g_gr[(size_t)c0 * 64 + lane * 2];
        float2 v1 = *(const float2*)&g_gr[(size_t)c1 * 64 + lane * 2];
        float2 v2 = *(const float2*)&g_gr[(size_t)c2 * 64 + lane * 2];
        float2 v3 = *(const float2*)&g_gr[(size_t)c3 * 64 + lane * 2];
        a0 += v0.x + v1.x + v2.x + v3.x;
        a1 += v0.y + v1.y + v2.y + v3.y;
    }
    for (; i < e; i++) {
        int c = __ldg(&g_dst[i]);
        float2 v = *(const float2*)&g_gr[(size_t)c * 64 + lane * 2];
        a0 += v.x; a1 += v.y;
    }
    size_t o = (size_t)gw * 64 + lane * 2;
    float2 gb = *(const float2*)&g_gbuf[o];
    float g0 = lrelu(gb.x + a0), g1 = lrelu(gb.y + a1);
    float s0 = g0 * __ldg(&wrel2[lane * 2]) + g1 * __ldg(&wrel2[lane * 2 + 1]);
    float s1 = g0 * __ldg(&wroot2[lane * 2]) + g1 * __ldg(&wroot2[lane * 2 + 1]);
#pragma unroll
    for (int off = 16; off; off >>= 1) {
        s0 += __shfl_xor_sync(0xffffffffu, s0, off);
        s1 += __shfl_xor_sync(0xffffffffu, s1, off);
    }
    if (lane == 0) {
        g_srel[gw] = s0;
        g_gate[gw] = s1 + __ldg(&bg2[0]);
    }
}

__global__ void gather_gate_kernel() {
    int gw = (blockIdx.x * blockDim.x + threadIdx.x) >> 5;
    int lane = threadIdx.x & 31;
    if (gw >= N_NODES) return;
    int s = g_rs[gw], e = g_rs[gw + 1];
    float acc = 0.f;
    for (int i = s + lane; i < e; i += 32) acc += g_srel[__ldg(&g_dst[i])];
#pragma unroll
    for (int off = 16; off; off >>= 1) acc += __shfl_xor_sync(0xffffffffu, acc, off);
    if (lane == 0) g_gate[gw] += acc;
}

// ---------------- per-edge cosine similarity ----------------
__global__ void edge_cos_kernel(const int* __restrict__ row, const int* __restrict__ col,
                                float* __restrict__ wmu) {
    int e = blockIdx.x * blockDim.x + threadIdx.x;
    if (e >= N_EDGES) return;
    int r = __ldg(&row[e]);
    int c = __ldg(&col[e]);
    const float4* a = (const float4*)&g_z[(size_t)r * 64];
    const float4* b = (const float4*)&g_z[(size_t)c * 64];
    float acc = 0.f;
#pragma unroll
    for (int i = 0; i < 16; i++) {
        float4 u = __ldg(a + i), v = __ldg(b + i);
        acc += u.x * v.x + u.y * v.y + u.z * v.z + u.w * v.w;
    }
    wmu[e] = acc / (g_norm[r] * g_norm[c]);
}

// ---------------- fused: sum exp + weighted pool + classifier (last block) ----------------
// 128 threads, 128 nodes per block: two 64-thread groups each handle 64 nodes.
__global__ __launch_bounds__(128)
void pool_final_kernel(const float* __restrict__ w_cls1, const float* __restrict__ b_cls1,
                       const float* __restrict__ w_cls2, const float* __restrict__ b_cls2,
                       const float* __restrict__ log_std, float* __restrict__ out) {
    __shared__ float part[2][64];
    __shared__ float psum[2];
    __shared__ float pooled[64], y1s[64], y2s[2];
    __shared__ int slast;
    int t = threadIdx.x;          // 0..127
    int col = t & 63, grp = t >> 6;
    int n0 = blockIdx.x * 128 + grp * 64;
    int n1 = n0 + 64; if (n1 > N_NODES) n1 = N_NODES;
    float acc = 0.f, sacc = 0.f;
    for (int n = n0; n < n1; n++) {
        float w = expf(g_gate[n]);   // bounded logits; shift-free exp safe
        acc += w * g_z[(size_t)n * 64 + col];
        if (col == 0) sacc += w;
    }
    part[grp][col] = acc;
    if (col == 0) psum[grp] = sacc;
    __syncthreads();
    if (t < 64) atomicAdd(&g_pool[t], part[0][t] + part[1][t]);
    if (t == 0) atomicAdd(&g_scal[1], psum[0] + psum[1]);
    __threadfence();
    __syncthreads();
    if (t == 0) slast = (atomicAdd(&g_poolcnt, 1) == gridDim.x - 1) ? 1 : 0;
    __syncthreads();
    if (!slast) return;

    if (t < 64) {
        float inv = 1.f / *((volatile float*)&g_scal[1]);
        pooled[t] = *((volatile float*)&g_pool[t]) * inv;
    }
    __syncthreads();
    if (t < 64) {
        float av = __ldg(&b_cls1[t]);
#pragma unroll
        for (int j = 0; j < 64; j++) av += pooled[j] * __ldg(&w_cls1[t * 64 + j]);
        y1s[t] = lrelu(av);
    }
    __syncthreads();
    if (t < 2) {
        float a = __ldg(&b_cls2[t]);
#pragma unroll
        for (int j = 0; j < 64; j++) a += y1s[j] * __ldg(&w_cls2[t * 64 + j]);
        y2s[t] = a;
    }
    __syncthreads();
    if (t == 0) {
        float m = fmaxf(y2s[0], y2s[1]);
        float e0 = expf(y2s[0] - m), e1 = expf(y2s[1] - m);
        out[0] = e0 / (e0 + e1);
        out[1] = e1 / (e0 + e1);
        out[2 + N_EDGES] = expf(__ldg(&log_std[0]));
        g_poolcnt = 0;
    }
}

// ---------------- launch ----------------
extern "C" void kernel_launch(void* const* d_in, const int* in_sizes, int n_in,
                              void* d_out, int out_size) {
    const float* x        = (const float*)d_in[0];
    const int*   row      = (const int*)d_in[1];
    const int*   col      = (const int*)d_in[2];
    const float* w_rel1   = (const float*)d_in[3];
    const float* w_root1  = (const float*)d_in[4];
    const float* b1       = (const float*)d_in[5];
    const float* w_rel_mu = (const float*)d_in[6];
    const float* w_root_mu= (const float*)d_in[7];
    const float* b_mu     = (const float*)d_in[8];
    const float* w_std    = (const float*)d_in[9];
    const float* b_std    = (const float*)d_in[10];
    const float* w_rel_g1 = (const float*)d_in[11];
    const float* w_root_g1= (const float*)d_in[12];
    const float* b_g1     = (const float*)d_in[13];
    const float* w_rel_g2 = (const float*)d_in[14];
    const float* w_root_g2= (const float*)d_in[15];
    const float* b_g2     = (const float*)d_in[16];
    const float* w_cls1   = (const float*)d_in[17];
    const float* b_cls1   = (const float*)d_in[18];
    const float* w_cls2   = (const float*)d_in[19];
    const float* b_cls2   = (const float*)d_in[20];
    const float* log_std  = (const float*)d_in[21];

    float* out       = (float*)d_out;
    float* out_wmu   = out + 2;
    float* out_z     = out + 3 + N_EDGES;
    float* out_zmu   = out_z + (size_t)N_NODES * 64;
    float* out_zstd  = out_zmu + (size_t)N_NODES * 64;

    const int MB = (N_NODES + 127) / 128;
    const int EB = (N_EDGES + 255) / 256;
    const int WB = (N_NODES * 32 + 255) / 256;
    const int PB = (N_NODES + 127) / 128;   // pool blocks (128 nodes each)

    const int SM1 = (2 * 128 * 40 * 2 + 2 * 128 * 40 * 2) * 2;  // 81920
    const int SM2 = (2 * 128 * 40 * 2 + 2 * 64 * 40 * 2) * 2;   // 61440

    static cudaStream_t s1 = nullptr;
    static cudaEvent_t ev_root = nullptr, ev_csr = nullptr, ev_h = nullptr,
                       ev_z = nullptr, ev_cos = nullptr;
    if (s1 == nullptr) {
        cudaStreamCreateWithFlags(&s1, cudaStreamNonBlocking);
        cudaEventCreateWithFlags(&ev_root, cudaEventDisableTiming);
        cudaEventCreateWithFlags(&ev_csr, cudaEventDisableTiming);
        cudaEventCreateWithFlags(&ev_h, cudaEventDisableTiming);
        cudaEventCreateWithFlags(&ev_z, cudaEventDisableTiming);
        cudaEventCreateWithFlags(&ev_cos, cudaEventDisableTiming);
        cudaFuncSetAttribute(mma_gemm_kernel<1>, cudaFuncAttributeMaxDynamicSharedMemorySize, SM1);
        cudaFuncSetAttribute(mma_gemm_kernel<2>, cudaFuncAttributeMaxDynamicSharedMemorySize, SM2);
        cudaFuncSetAttribute(mma_gemm_kernel<3>, cudaFuncAttributeMaxDynamicSharedMemorySize, SM2);
        cudaFuncSetAttribute(mma_gemm_kernel<4>, cudaFuncAttributeMaxDynamicSharedMemorySize, SM2);
    }

    // ---- fork 1: CSR build on s1 || gemm1 on main ----
    cudaEventRecord(ev_root, 0);
    cudaStreamWaitEvent(s1, ev_root, 0);

    hist_kernel<<<EB, 256, 0, s1>>>(row);
    bsum_kernel<<<NB_SCAN, 256, 0, s1>>>();
    lscan2_kernel<<<NB_SCAN, 256, 0, s1>>>();
    fill_kernel<<<EB, 256, 0, s1>>>(row, col);
    cudaEventRecord(ev_csr, s1);

    mma_gemm_kernel<1><<<dim3(2, MB), 256, SM1>>>(x, w_rel1, w_root1, b1, nullptr);

    cudaStreamWaitEvent(0, ev_csr, 0);
    gather_h_kernel<<<WB, 256>>>();
    cudaEventRecord(ev_h, 0);

    // std head on s1 (only needs g_h; writes out_zstd)
    cudaStreamWaitEvent(s1, ev_h, 0);
    mma_gemm_kernel<4><<<dim3(1, MB), 256, SM2, s1>>>(nullptr, w_std, nullptr, b_std, out_zstd);

    // layer 2 main (mu heads)
    mma_gemm_kernel<2><<<dim3(2, MB), 256, SM2>>>(nullptr, w_rel_mu, w_root_mu, b_mu, nullptr);
    gather_z_kernel<<<WB, 256>>>();
    cudaEventRecord(ev_z, 0);

    // ---- fork 2: z copies + edge cosine on s1 || gating chain on main ----
    cudaStreamWaitEvent(s1, ev_z, 0);
    copyz_kernel<<<(N_NODES * 64 + 255) / 256, 256, 0, s1>>>(out_z, out_zmu);
    edge_cos_kernel<<<EB, 256, 0, s1>>>(row, col, out_wmu);
    cudaEventRecord(ev_cos, s1);

    mma_gemm_kernel<3><<<dim3(2, MB), 256, SM2>>>(nullptr, w_rel_g1, w_root_g1, b_g1, nullptr);
    gather_g_kernel<<<WB, 256>>>(w_rel_g2, w_root_g2, b_g2);
    gather_gate_kernel<<<WB, 256>>>();
    pool_final_kernel<<<PB, 128>>>(w_cls1, b_cls1, w_cls2, b_cls2, log_std, out);

    cudaStreamWaitEvent(0, ev_cos, 0);
}